// round 4
// baseline (speedup 1.0000x reference)
#include <cuda_runtime.h>
#include <math.h>

#define T_TOK 1024
#define HDIM  2048
#define NEXP  16
#define KSEL  4
#define IDIM  1408
#define ISDIM 2816

typedef unsigned long long u64;

// packed fp32x2 FMA: acc.lo += a.lo*b.lo ; acc.hi += a.hi*b.hi  (exact fp32 lanewise)
#define FMA2(acc, a, b) asm("fma.rn.f32x2 %0, %1, %2, %0;" : "+l"(acc) : "l"(a), "l"(b))

__device__ __forceinline__ float lo32(u64 v) { return __uint_as_float((unsigned)v); }
__device__ __forceinline__ float hi32(u64 v) { return __uint_as_float((unsigned)(v >> 32)); }

// ---------------- scratch (static device globals; no allocation APIs) ----------------
__device__ int   g_counts[NEXP];
__device__ int   g_tokens[NEXP * T_TOK];
__device__ float g_wts[NEXP * T_TOK];
__device__ float g_act[(size_t)NEXP * T_TOK * IDIM];   // routed SwiGLU activations, grouped by expert
__device__ float g_acts[(size_t)T_TOK * ISDIM];        // shared-expert SwiGLU activations

// ---------------- kernel 0: reset per-expert counters ----------------
__global__ void zero_counts_kernel() {
    if (threadIdx.x < NEXP) g_counts[threadIdx.x] = 0;
}

// ---------------- kernel 1: router (softmax -> top-4 -> renorm -> scatter) ----------------
__global__ void gate_kernel(const float* __restrict__ x, const float* __restrict__ gw) {
    int t = blockIdx.x;
    __shared__ float xs[HDIM];
    __shared__ float logits[NEXP];
    const float* xrow = x + (size_t)t * HDIM;
    for (int i = threadIdx.x; i < HDIM; i += blockDim.x) xs[i] = xrow[i];
    __syncthreads();

    int warp = threadIdx.x >> 5, lane = threadIdx.x & 31;
    for (int e = warp; e < NEXP; e += 8) {
        const float* grow = gw + (size_t)e * HDIM;
        float s = 0.f;
        for (int h = lane; h < HDIM; h += 32) s += xs[h] * grow[h];
        #pragma unroll
        for (int o = 16; o > 0; o >>= 1) s += __shfl_xor_sync(0xffffffffu, s, o);
        if (lane == 0) logits[e] = s;
    }
    __syncthreads();

    if (threadIdx.x == 0) {
        float mx = -1e30f;
        for (int e = 0; e < NEXP; e++) mx = fmaxf(mx, logits[e]);
        float sc[NEXP]; float se = 0.f;
        for (int e = 0; e < NEXP; e++) { sc[e] = expf(logits[e] - mx); se += sc[e]; }
        float inv = 1.f / se;
        for (int e = 0; e < NEXP; e++) sc[e] *= inv;

        int   idx[KSEL]; float w[KSEL]; float wsum = 0.f;
        bool used[NEXP];
        for (int e = 0; e < NEXP; e++) used[e] = false;
        for (int k = 0; k < KSEL; k++) {
            int best = 0; float bv = -1.f;
            for (int e = 0; e < NEXP; e++)
                if (!used[e] && sc[e] > bv) { bv = sc[e]; best = e; }
            used[best] = true; idx[k] = best; w[k] = bv; wsum += bv;
        }
        float iw = 1.f / wsum;
        for (int k = 0; k < KSEL; k++) {
            int e = idx[k];
            int pos = atomicAdd(&g_counts[e], 1);
            g_tokens[e * T_TOK + pos] = t;
            g_wts[e * T_TOK + pos]    = w[k] * iw;
        }
    }
}

// ---------------- kernel 2: gate/up GEMM + SwiGLU epilogue (f32x2 packed) ----------------
// C-tile 128x64. Accumulators packed along row pairs; B duplicated in smem so a
// single LDS.128 yields broadcast pairs {b0,b0},{b1,b1}.
__global__ __launch_bounds__(256, 2)
void up_gemm_kernel(const float* __restrict__ X,
                    const float* __restrict__ Wg, const float* __restrict__ Wu,
                    long wExpStride, int ldB, int routed)
{
    int e = blockIdx.z;
    int count = routed ? g_counts[e] : T_TOK;
    int m0 = blockIdx.y * 128;
    if (m0 >= count) return;
    int n0 = blockIdx.x * 64;
    const int Kdim = HDIM;

    const float* Bg = Wg + (size_t)e * wExpStride + n0;
    const float* Bu = Wu + (size_t)e * wExpStride + n0;
    const int* toks = routed ? (g_tokens + e * T_TOK) : nullptr;

    __shared__ __align__(16) float As[16][128];   // col-major A slab (k x rows)
    __shared__ __align__(16) float Sg[16][128];   // duplicated B: [b0,b0,b1,b1,...]
    __shared__ __align__(16) float Su[16][128];

    int tid = threadIdx.x;
    int tx = tid & 15, ty = tid >> 4;

    // A loaders: 128x16 = 512 float4, 2 per thread
    int arow0 = tid >> 2;
    int arow1 = arow0 + 64;
    int ac4   = (tid & 3) * 4;
    bool v0 = (m0 + arow0) < count;
    bool v1 = (m0 + arow1) < count;
    int tok0 = v0 ? (routed ? toks[m0 + arow0] : (m0 + arow0)) : 0;
    int tok1 = v1 ? (routed ? toks[m0 + arow1] : (m0 + arow1)) : 0;
    const float* xp0 = X + (size_t)tok0 * Kdim + ac4;
    const float* xp1 = X + (size_t)tok1 * Kdim + ac4;

    // B loaders: 16x64 = 256 float4, 1 per thread (each of g/u)
    int brow = tid >> 4;
    int bc4  = (tid & 15) * 4;
    const float* bgp = Bg + (size_t)brow * ldB + bc4;
    const float* bup = Bu + (size_t)brow * ldB + bc4;

    u64 accg[4][4], accu[4][4];
    #pragma unroll
    for (int i = 0; i < 4; i++)
        #pragma unroll
        for (int j = 0; j < 4; j++) { accg[i][j] = 0ull; accu[i][j] = 0ull; }

    // preload k0 = 0
    float4 ra0 = v0 ? *(const float4*)(xp0) : make_float4(0.f, 0.f, 0.f, 0.f);
    float4 ra1 = v1 ? *(const float4*)(xp1) : make_float4(0.f, 0.f, 0.f, 0.f);
    float4 rbg = *(const float4*)(bgp);
    float4 rbu = *(const float4*)(bup);

    for (int k0 = 0; k0 < Kdim; k0 += 16) {
        __syncthreads();
        As[ac4 + 0][arow0] = ra0.x; As[ac4 + 1][arow0] = ra0.y;
        As[ac4 + 2][arow0] = ra0.z; As[ac4 + 3][arow0] = ra0.w;
        As[ac4 + 0][arow1] = ra1.x; As[ac4 + 1][arow1] = ra1.y;
        As[ac4 + 2][arow1] = ra1.z; As[ac4 + 3][arow1] = ra1.w;
        // duplicated B writes
        *(float4*)&Sg[brow][bc4 * 2]     = make_float4(rbg.x, rbg.x, rbg.y, rbg.y);
        *(float4*)&Sg[brow][bc4 * 2 + 4] = make_float4(rbg.z, rbg.z, rbg.w, rbg.w);
        *(float4*)&Su[brow][bc4 * 2]     = make_float4(rbu.x, rbu.x, rbu.y, rbu.y);
        *(float4*)&Su[brow][bc4 * 2 + 4] = make_float4(rbu.z, rbu.z, rbu.w, rbu.w);
        __syncthreads();

        // prefetch next slab (latency hidden behind compute)
        int kn = k0 + 16;
        if (kn < Kdim) {
            ra0 = v0 ? *(const float4*)(xp0 + kn) : make_float4(0.f, 0.f, 0.f, 0.f);
            ra1 = v1 ? *(const float4*)(xp1 + kn) : make_float4(0.f, 0.f, 0.f, 0.f);
            rbg = *(const float4*)(bgp + (size_t)kn * ldB);
            rbu = *(const float4*)(bup + (size_t)kn * ldB);
        }

        #pragma unroll
        for (int kk = 0; kk < 16; kk++) {
            ulonglong2 aA = *(const ulonglong2*)&As[kk][ty * 8];
            ulonglong2 aB = *(const ulonglong2*)&As[kk][ty * 8 + 4];
            ulonglong2 g01 = *(const ulonglong2*)&Sg[kk][tx * 8];
            ulonglong2 g23 = *(const ulonglong2*)&Sg[kk][tx * 8 + 4];
            ulonglong2 u01 = *(const ulonglong2*)&Su[kk][tx * 8];
            ulonglong2 u23 = *(const ulonglong2*)&Su[kk][tx * 8 + 4];
            u64 a[4]  = { aA.x, aA.y, aB.x, aB.y };
            u64 bg[4] = { g01.x, g01.y, g23.x, g23.y };
            u64 bu[4] = { u01.x, u01.y, u23.x, u23.y };
            #pragma unroll
            for (int i = 0; i < 4; i++)
                #pragma unroll
                for (int j = 0; j < 4; j++) {
                    FMA2(accg[i][j], a[i], bg[j]);
                    FMA2(accu[i][j], a[i], bu[j]);
                }
        }
    }

    float* actBase = routed ? (g_act + (size_t)e * T_TOK * IDIM) : g_acts;
    int actLd = routed ? IDIM : ISDIM;
    #pragma unroll
    for (int ip = 0; ip < 4; ip++) {
        int r0 = ty * 8 + ip * 2;
        #pragma unroll
        for (int half = 0; half < 2; half++) {
            int m = m0 + r0 + half;
            if (m >= count) continue;
            float w = routed ? g_wts[e * T_TOK + m] : 1.0f;
            float vals[4];
            #pragma unroll
            for (int j = 0; j < 4; j++) {
                float g = half ? hi32(accg[ip][j]) : lo32(accg[ip][j]);
                float u = half ? hi32(accu[ip][j]) : lo32(accu[ip][j]);
                float s = g / (1.f + expf(-g));   // silu
                vals[j] = s * u * w;
            }
            *(float4*)&actBase[(size_t)m * actLd + n0 + tx * 4] = *(float4*)vals;
        }
    }
}

// ---------------- kernel 3: down-proj GEMM (f32x2 packed) ----------------
__global__ __launch_bounds__(256, 2)
void down_gemm_kernel(const float* __restrict__ Wd, long wExpStride,
                      float* __restrict__ out, int routed)
{
    int e = blockIdx.z;
    int count = routed ? g_counts[e] : T_TOK;
    int m0 = blockIdx.y * 128;
    if (m0 >= count) return;
    int n0 = blockIdx.x * 64;
    int Kdim = routed ? IDIM : ISDIM;

    const float* A = routed ? (g_act + (size_t)e * T_TOK * IDIM) : g_acts;
    int lda = Kdim;
    const float* B = Wd + (size_t)e * wExpStride + n0;   // row stride HDIM

    __shared__ __align__(16) float As[16][128];
    __shared__ __align__(16) float Bs[16][128];   // duplicated

    int tid = threadIdx.x;
    int tx = tid & 15, ty = tid >> 4;

    int arow0 = tid >> 2;
    int arow1 = arow0 + 64;
    int ac4   = (tid & 3) * 4;
    bool v0 = (m0 + arow0) < count;
    bool v1 = (m0 + arow1) < count;
    const float* ap0 = A + (size_t)(m0 + arow0) * lda + ac4;
    const float* ap1 = A + (size_t)(m0 + arow1) * lda + ac4;

    int brow = tid >> 4;
    int bc4  = (tid & 15) * 4;
    const float* bp = B + (size_t)brow * HDIM + bc4;

    u64 acc[4][4];
    #pragma unroll
    for (int i = 0; i < 4; i++)
        #pragma unroll
        for (int j = 0; j < 4; j++) acc[i][j] = 0ull;

    float4 ra0 = v0 ? *(const float4*)(ap0) : make_float4(0.f, 0.f, 0.f, 0.f);
    float4 ra1 = v1 ? *(const float4*)(ap1) : make_float4(0.f, 0.f, 0.f, 0.f);
    float4 rb  = *(const float4*)(bp);

    for (int k0 = 0; k0 < Kdim; k0 += 16) {
        __syncthreads();
        As[ac4 + 0][arow0] = ra0.x; As[ac4 + 1][arow0] = ra0.y;
        As[ac4 + 2][arow0] = ra0.z; As[ac4 + 3][arow0] = ra0.w;
        As[ac4 + 0][arow1] = ra1.x; As[ac4 + 1][arow1] = ra1.y;
        As[ac4 + 2][arow1] = ra1.z; As[ac4 + 3][arow1] = ra1.w;
        *(float4*)&Bs[brow][bc4 * 2]     = make_float4(rb.x, rb.x, rb.y, rb.y);
        *(float4*)&Bs[brow][bc4 * 2 + 4] = make_float4(rb.z, rb.z, rb.w, rb.w);
        __syncthreads();

        int kn = k0 + 16;
        if (kn < Kdim) {
            ra0 = v0 ? *(const float4*)(ap0 + kn) : make_float4(0.f, 0.f, 0.f, 0.f);
            ra1 = v1 ? *(const float4*)(ap1 + kn) : make_float4(0.f, 0.f, 0.f, 0.f);
            rb  = *(const float4*)(bp + (size_t)kn * HDIM);
        }

        #pragma unroll
        for (int kk = 0; kk < 16; kk++) {
            ulonglong2 aA = *(const ulonglong2*)&As[kk][ty * 8];
            ulonglong2 aB = *(const ulonglong2*)&As[kk][ty * 8 + 4];
            ulonglong2 b01 = *(const ulonglong2*)&Bs[kk][tx * 8];
            ulonglong2 b23 = *(const ulonglong2*)&Bs[kk][tx * 8 + 4];
            u64 a[4] = { aA.x, aA.y, aB.x, aB.y };
            u64 b[4] = { b01.x, b01.y, b23.x, b23.y };
            #pragma unroll
            for (int i = 0; i < 4; i++)
                #pragma unroll
                for (int j = 0; j < 4; j++)
                    FMA2(acc[i][j], a[i], b[j]);
        }
    }

    const int* toks = routed ? (g_tokens + e * T_TOK) : nullptr;
    #pragma unroll
    for (int ip = 0; ip < 4; ip++) {
        int r0 = ty * 8 + ip * 2;
        #pragma unroll
        for (int half = 0; half < 2; half++) {
            int m = m0 + r0 + half;
            if (m >= count) continue;
            float vals[4];
            #pragma unroll
            for (int j = 0; j < 4; j++)
                vals[j] = half ? hi32(acc[ip][j]) : lo32(acc[ip][j]);
            if (routed) {
                int t = toks[m];
                float* op = out + (size_t)t * HDIM + n0 + tx * 4;
                #pragma unroll
                for (int j = 0; j < 4; j++) atomicAdd(op + j, vals[j]);
            } else {
                *(float4*)(out + (size_t)m * HDIM + n0 + tx * 4) = *(float4*)vals;
            }
        }
    }
}

// ---------------- launch ----------------
extern "C" void kernel_launch(void* const* d_in, const int* in_sizes, int n_in,
                              void* d_out, int out_size) {
    (void)in_sizes; (void)n_in; (void)out_size;
    const float* x       = (const float*)d_in[0];
    const float* gate_w  = (const float*)d_in[1];
    const float* w_gate  = (const float*)d_in[2];
    const float* w_up    = (const float*)d_in[3];
    const float* w_down  = (const float*)d_in[4];
    const float* sw_gate = (const float*)d_in[5];
    const float* sw_up   = (const float*)d_in[6];
    const float* sw_down = (const float*)d_in[7];
    float* out = (float*)d_out;

    zero_counts_kernel<<<1, 32>>>();
    gate_kernel<<<T_TOK, 256>>>(x, gate_w);

    dim3 g1r(IDIM / 64, T_TOK / 128, NEXP);
    up_gemm_kernel<<<g1r, 256>>>(x, w_gate, w_up, (long)HDIM * IDIM, IDIM, 1);

    dim3 g1s(ISDIM / 64, T_TOK / 128, 1);
    up_gemm_kernel<<<g1s, 256>>>(x, sw_gate, sw_up, 0L, ISDIM, 0);

    dim3 g2s(HDIM / 64, T_TOK / 128, 1);
    down_gemm_kernel<<<g2s, 256>>>(sw_down, 0L, out, 0);

    dim3 g2r(HDIM / 64, T_TOK / 128, NEXP);
    down_gemm_kernel<<<g2r, 256>>>(w_down, (long)IDIM * HDIM, out, 1);
}

// round 6
// speedup vs baseline: 1.8707x; 1.8707x over previous
#include <cuda_runtime.h>
#include <math.h>

#define T_TOK 1024
#define HDIM  2048
#define NEXP  16
#define KSEL  4
#define IDIM  1408
#define ISDIM 2816

typedef unsigned long long u64;

// packed fp32x2 FMA: acc.lo += a.lo*b.lo ; acc.hi += a.hi*b.hi (exact fp32 lanewise)
#define FMA2(acc, a, b) asm("fma.rn.f32x2 %0, %1, %2, %0;" : "+l"(acc) : "l"(a), "l"(b))

__device__ __forceinline__ u64 bcast(float x) {
    u64 r; asm("mov.b64 %0, {%1, %1};" : "=l"(r) : "f"(x)); return r;
}
__device__ __forceinline__ float lo32(u64 v) { return __uint_as_float((unsigned)v); }
__device__ __forceinline__ float hi32(u64 v) { return __uint_as_float((unsigned)(v >> 32)); }

// ---------------- scratch ----------------
__device__ int   g_counts[NEXP];
__device__ int   g_tokens[NEXP * T_TOK];
__device__ float g_wts[NEXP * T_TOK];
__device__ float g_act[(size_t)NEXP * T_TOK * IDIM];
__device__ float g_acts[(size_t)T_TOK * ISDIM];

__global__ void zero_counts_kernel() {
    if (threadIdx.x < NEXP) g_counts[threadIdx.x] = 0;
}

// ---------------- router ----------------
__global__ void gate_kernel(const float* __restrict__ x, const float* __restrict__ gw) {
    int t = blockIdx.x;
    __shared__ float xs[HDIM];
    __shared__ float logits[NEXP];
    const float* xrow = x + (size_t)t * HDIM;
    for (int i = threadIdx.x; i < HDIM; i += blockDim.x) xs[i] = xrow[i];
    __syncthreads();

    int warp = threadIdx.x >> 5, lane = threadIdx.x & 31;
    for (int e = warp; e < NEXP; e += 8) {
        const float* grow = gw + (size_t)e * HDIM;
        float s = 0.f;
        for (int h = lane; h < HDIM; h += 32) s += xs[h] * grow[h];
        #pragma unroll
        for (int o = 16; o > 0; o >>= 1) s += __shfl_xor_sync(0xffffffffu, s, o);
        if (lane == 0) logits[e] = s;
    }
    __syncthreads();

    if (threadIdx.x == 0) {
        float mx = -1e30f;
        for (int e = 0; e < NEXP; e++) mx = fmaxf(mx, logits[e]);
        float sc[NEXP]; float se = 0.f;
        for (int e = 0; e < NEXP; e++) { sc[e] = expf(logits[e] - mx); se += sc[e]; }
        float inv = 1.f / se;
        for (int e = 0; e < NEXP; e++) sc[e] *= inv;

        int idx[KSEL]; float w[KSEL]; float wsum = 0.f;
        bool used[NEXP];
        for (int e = 0; e < NEXP; e++) used[e] = false;
        for (int k = 0; k < KSEL; k++) {
            int best = 0; float bv = -1.f;
            for (int e = 0; e < NEXP; e++)
                if (!used[e] && sc[e] > bv) { bv = sc[e]; best = e; }
            used[best] = true; idx[k] = best; w[k] = bv; wsum += bv;
        }
        float iw = 1.f / wsum;
        for (int k = 0; k < KSEL; k++) {
            int e = idx[k];
            int pos = atomicAdd(&g_counts[e], 1);
            g_tokens[e * T_TOK + pos] = t;
            g_wts[e * T_TOK + pos]    = w[k] * iw;
        }
    }
}

// ---------------- gate/up GEMM + SwiGLU (f32x2, register-broadcast B) ----------------
// C-tile 128x64, both g and u. acc packed along M row pairs.
__global__ __launch_bounds__(256, 2)
void up_gemm_kernel(const float* __restrict__ X,
                    const float* __restrict__ Wg, const float* __restrict__ Wu,
                    long wExpStride, int ldB, int routed)
{
    int e = blockIdx.z;
    int count = routed ? g_counts[e] : T_TOK;
    int m0 = blockIdx.y * 128;
    if (m0 >= count) return;
    int n0 = blockIdx.x * 64;
    const int Kdim = HDIM;

    const float* Bg = Wg + (size_t)e * wExpStride + n0;
    const float* Bu = Wu + (size_t)e * wExpStride + n0;
    const int* toks = routed ? (g_tokens + e * T_TOK) : nullptr;

    __shared__ __align__(16) float As[16][128];   // col-major A slab
    __shared__ __align__(16) float Sg[16][64];
    __shared__ __align__(16) float Su[16][64];

    int tid = threadIdx.x;
    int tx = tid & 15, ty = tid >> 4;

    int arow0 = tid >> 2;
    int arow1 = arow0 + 64;
    int ac4   = (tid & 3) * 4;
    bool v0 = (m0 + arow0) < count;
    bool v1 = (m0 + arow1) < count;
    int tok0 = v0 ? (routed ? toks[m0 + arow0] : (m0 + arow0)) : 0;
    int tok1 = v1 ? (routed ? toks[m0 + arow1] : (m0 + arow1)) : 0;
    const float* xp0 = X + (size_t)tok0 * Kdim + ac4;
    const float* xp1 = X + (size_t)tok1 * Kdim + ac4;

    int brow = tid >> 4;
    int bc4  = (tid & 15) * 4;
    const float* bgp = Bg + (size_t)brow * ldB + bc4;
    const float* bup = Bu + (size_t)brow * ldB + bc4;

    u64 accg[4][4], accu[4][4];
    #pragma unroll
    for (int i = 0; i < 4; i++)
        #pragma unroll
        for (int j = 0; j < 4; j++) { accg[i][j] = 0ull; accu[i][j] = 0ull; }

    float4 ra0 = v0 ? *(const float4*)(xp0) : make_float4(0.f, 0.f, 0.f, 0.f);
    float4 ra1 = v1 ? *(const float4*)(xp1) : make_float4(0.f, 0.f, 0.f, 0.f);
    float4 rbg = *(const float4*)(bgp);
    float4 rbu = *(const float4*)(bup);

    for (int k0 = 0; k0 < Kdim; k0 += 16) {
        __syncthreads();
        As[ac4 + 0][arow0] = ra0.x; As[ac4 + 1][arow0] = ra0.y;
        As[ac4 + 2][arow0] = ra0.z; As[ac4 + 3][arow0] = ra0.w;
        As[ac4 + 0][arow1] = ra1.x; As[ac4 + 1][arow1] = ra1.y;
        As[ac4 + 2][arow1] = ra1.z; As[ac4 + 3][arow1] = ra1.w;
        *(float4*)&Sg[brow][bc4] = rbg;
        *(float4*)&Su[brow][bc4] = rbu;
        __syncthreads();

        int kn = k0 + 16;
        if (kn < Kdim) {
            ra0 = v0 ? *(const float4*)(xp0 + kn) : make_float4(0.f, 0.f, 0.f, 0.f);
            ra1 = v1 ? *(const float4*)(xp1 + kn) : make_float4(0.f, 0.f, 0.f, 0.f);
            rbg = *(const float4*)(bgp + (size_t)kn * ldB);
            rbu = *(const float4*)(bup + (size_t)kn * ldB);
        }

        #pragma unroll
        for (int kk = 0; kk < 16; kk++) {
            ulonglong2 aA = *(const ulonglong2*)&As[kk][ty * 8];
            ulonglong2 aB = *(const ulonglong2*)&As[kk][ty * 8 + 4];
            u64 a[4] = { aA.x, aA.y, aB.x, aB.y };
            float4 bg4 = *(const float4*)&Sg[kk][tx * 4];
            float4 bu4 = *(const float4*)&Su[kk][tx * 4];
            u64 bg[4] = { bcast(bg4.x), bcast(bg4.y), bcast(bg4.z), bcast(bg4.w) };
            u64 bu[4] = { bcast(bu4.x), bcast(bu4.y), bcast(bu4.z), bcast(bu4.w) };
            #pragma unroll
            for (int i = 0; i < 4; i++)
                #pragma unroll
                for (int j = 0; j < 4; j++) {
                    FMA2(accg[i][j], a[i], bg[j]);
                    FMA2(accu[i][j], a[i], bu[j]);
                }
        }
    }

    float* actBase = routed ? (g_act + (size_t)e * T_TOK * IDIM) : g_acts;
    int actLd = routed ? IDIM : ISDIM;
    #pragma unroll
    for (int ip = 0; ip < 4; ip++) {
        #pragma unroll
        for (int half = 0; half < 2; half++) {
            int m = m0 + ty * 8 + ip * 2 + half;
            if (m >= count) continue;
            float w = routed ? g_wts[e * T_TOK + m] : 1.0f;
            float vals[4];
            #pragma unroll
            for (int j = 0; j < 4; j++) {
                float g = half ? hi32(accg[ip][j]) : lo32(accg[ip][j]);
                float u = half ? hi32(accu[ip][j]) : lo32(accu[ip][j]);
                float s = g / (1.f + expf(-g));
                vals[j] = s * u * w;
            }
            *(float4*)&actBase[(size_t)m * actLd + n0 + tx * 4] = *(float4*)vals;
        }
    }
}

// ---------------- down-proj GEMM (f32x2, 128x128 tile) ----------------
// Per-thread: 4 row-pairs x 8 cols; cols split {tx*4, 64+tx*4} for conflict-free LDS.
__global__ __launch_bounds__(256, 2)
void down_gemm_kernel(const float* __restrict__ Wd, long wExpStride,
                      float* __restrict__ out, int routed)
{
    int e = blockIdx.z;
    int count = routed ? g_counts[e] : T_TOK;
    int m0 = blockIdx.y * 128;
    if (m0 >= count) return;
    int n0 = blockIdx.x * 128;
    int Kdim = routed ? IDIM : ISDIM;

    const float* A = routed ? (g_act + (size_t)e * T_TOK * IDIM) : g_acts;
    int lda = Kdim;
    const float* B = Wd + (size_t)e * wExpStride + n0;   // row stride HDIM

    __shared__ __align__(16) float As[16][128];
    __shared__ __align__(16) float Bs[16][128];

    int tid = threadIdx.x;
    int tx = tid & 15, ty = tid >> 4;

    int arow0 = tid >> 2;
    int arow1 = arow0 + 64;
    int ac4   = (tid & 3) * 4;
    bool v0 = (m0 + arow0) < count;
    bool v1 = (m0 + arow1) < count;
    const float* ap0 = A + (size_t)(m0 + arow0) * lda + ac4;
    const float* ap1 = A + (size_t)(m0 + arow1) * lda + ac4;

    int brow = tid >> 4;
    int bc8  = (tid & 15) * 8;
    const float* bp = B + (size_t)brow * HDIM + bc8;

    u64 acc[4][8];
    #pragma unroll
    for (int i = 0; i < 4; i++)
        #pragma unroll
        for (int j = 0; j < 8; j++) acc[i][j] = 0ull;

    float4 ra0 = v0 ? *(const float4*)(ap0) : make_float4(0.f, 0.f, 0.f, 0.f);
    float4 ra1 = v1 ? *(const float4*)(ap1) : make_float4(0.f, 0.f, 0.f, 0.f);
    float4 rb0 = *(const float4*)(bp);
    float4 rb1 = *(const float4*)(bp + 4);

    for (int k0 = 0; k0 < Kdim; k0 += 16) {
        __syncthreads();
        As[ac4 + 0][arow0] = ra0.x; As[ac4 + 1][arow0] = ra0.y;
        As[ac4 + 2][arow0] = ra0.z; As[ac4 + 3][arow0] = ra0.w;
        As[ac4 + 0][arow1] = ra1.x; As[ac4 + 1][arow1] = ra1.y;
        As[ac4 + 2][arow1] = ra1.z; As[ac4 + 3][arow1] = ra1.w;
        *(float4*)&Bs[brow][bc8]     = rb0;
        *(float4*)&Bs[brow][bc8 + 4] = rb1;
        __syncthreads();

        int kn = k0 + 16;
        if (kn < Kdim) {
            ra0 = v0 ? *(const float4*)(ap0 + kn) : make_float4(0.f, 0.f, 0.f, 0.f);
            ra1 = v1 ? *(const float4*)(ap1 + kn) : make_float4(0.f, 0.f, 0.f, 0.f);
            rb0 = *(const float4*)(bp + (size_t)kn * HDIM);
            rb1 = *(const float4*)(bp + (size_t)kn * HDIM + 4);
        }

        #pragma unroll
        for (int kk = 0; kk < 16; kk++) {
            ulonglong2 aA = *(const ulonglong2*)&As[kk][ty * 8];
            ulonglong2 aB = *(const ulonglong2*)&As[kk][ty * 8 + 4];
            u64 a[4] = { aA.x, aA.y, aB.x, aB.y };
            float4 b0 = *(const float4*)&Bs[kk][tx * 4];        // cols tx*4..+3
            float4 b1 = *(const float4*)&Bs[kk][64 + tx * 4];   // cols 64+tx*4..+3
            u64 b[8] = { bcast(b0.x), bcast(b0.y), bcast(b0.z), bcast(b0.w),
                         bcast(b1.x), bcast(b1.y), bcast(b1.z), bcast(b1.w) };
            #pragma unroll
            for (int i = 0; i < 4; i++)
                #pragma unroll
                for (int j = 0; j < 8; j++)
                    FMA2(acc[i][j], a[i], b[j]);
        }
    }

    const int* toks = routed ? (g_tokens + e * T_TOK) : nullptr;
    #pragma unroll
    for (int ip = 0; ip < 4; ip++) {
        #pragma unroll
        for (int half = 0; half < 2; half++) {
            int m = m0 + ty * 8 + ip * 2 + half;
            if (m >= count) continue;
            float vals0[4], vals1[4];
            #pragma unroll
            for (int j = 0; j < 4; j++) {
                vals0[j] = half ? hi32(acc[ip][j])     : lo32(acc[ip][j]);
                vals1[j] = half ? hi32(acc[ip][j + 4]) : lo32(acc[ip][j + 4]);
            }
            if (routed) {
                int t = toks[m];
                float* op = out + (size_t)t * HDIM + n0;
                #pragma unroll
                for (int j = 0; j < 4; j++) {
                    atomicAdd(op + tx * 4 + j,      vals0[j]);
                    atomicAdd(op + 64 + tx * 4 + j, vals1[j]);
                }
            } else {
                float* op = out + (size_t)m * HDIM + n0;
                *(float4*)(op + tx * 4)      = *(float4*)vals0;
                *(float4*)(op + 64 + tx * 4) = *(float4*)vals1;
            }
        }
    }
}

// ---------------- launch ----------------
extern "C" void kernel_launch(void* const* d_in, const int* in_sizes, int n_in,
                              void* d_out, int out_size) {
    (void)in_sizes; (void)n_in; (void)out_size;
    const float* x       = (const float*)d_in[0];
    const float* gate_w  = (const float*)d_in[1];
    const float* w_gate  = (const float*)d_in[2];
    const float* w_up    = (const float*)d_in[3];
    const float* w_down  = (const float*)d_in[4];
    const float* sw_gate = (const float*)d_in[5];
    const float* sw_up   = (const float*)d_in[6];
    const float* sw_down = (const float*)d_in[7];
    float* out = (float*)d_out;

    zero_counts_kernel<<<1, 32>>>();
    gate_kernel<<<T_TOK, 256>>>(x, gate_w);

    dim3 g1r(IDIM / 64, T_TOK / 128, NEXP);
    up_gemm_kernel<<<g1r, 256>>>(x, w_gate, w_up, (long)HDIM * IDIM, IDIM, 1);

    dim3 g1s(ISDIM / 64, T_TOK / 128, 1);
    up_gemm_kernel<<<g1s, 256>>>(x, sw_gate, sw_up, 0L, ISDIM, 0);

    dim3 g2s(HDIM / 128, T_TOK / 128, 1);
    down_gemm_kernel<<<g2s, 256>>>(sw_down, 0L, out, 0);

    dim3 g2r(HDIM / 128, T_TOK / 128, NEXP);
    down_gemm_kernel<<<g2r, 256>>>(w_down, (long)IDIM * HDIM, out, 1);
}